// round 15
// baseline (speedup 1.0000x reference)
#include <cuda_runtime.h>
#include <cuda_fp16.h>
#include <math.h>
#include <stdint.h>

#define NB 4
#define NPER 4096
#define EPER 49152
#define NN (NB*NPER)        // 16384 nodes
#define ETOT (NB*EPER)      // 196608 edges
#define F 128
#define KF 20
#define NL 3
#define CUTF 5.0f
#define PIF 3.14159265358979323846f

#define LDW1 136            // row stride (elems) for K=128 planes
#define LDW2 264            // row stride for K=256 planes

// ------------- fp16 weight arena (packed once per launch) -------------------
#define OFF_IW1 0
#define SZ_IW1 (128*LDW2)
#define OFF_IW2 (OFF_IW1 + SZ_IW1)
#define SZ_IW2 (128*LDW1)
#define OFF_LBASE (OFF_IW2 + SZ_IW2)
#define LOFF_MW1 0
#define LOFF_MW2 (128*LDW1)
#define LOFF_UW1 (LOFF_MW2 + 384*LDW1)
#define LOFF_UW2 (LOFF_UW1 + 128*LDW2)
#define LOFF_UVW (LOFF_UW2 + 384*LDW1)
#define LSTRIDE  (LOFF_UVW + 256*LDW1)
#define WARENA   (OFF_LBASE + NL*LSTRIDE)

__device__ __align__(16) __half g_WSF[WARENA];

// ---------------- scratch -----------------------------------------------------
__device__ __align__(16) float g_s  [NN*F];
__device__ __align__(16) float g_v  [NN*3*F];
__device__ __align__(16) float g_ds [NN*F];
__device__ __align__(16) float g_dv [NN*3*F];
__device__ __align__(16) __half g_soF[NN*3*F];     // fp16 message-MLP output
__device__ __align__(16) __half g_mF [NN*3*F];     // fp16 update-MLP output
__device__ __align__(16) __half g_UVo[NN*3*256];   // fp16 Uv|Vv
__device__ __align__(16) float g_dot[NN*F];
__device__ __align__(16) float g_es [ETOT*KF];
__device__ float g_cut[ETOT];
__device__ float g_dir[ETOT*3];
__device__ int   g_send[ETOT];
__device__ int   g_recv[ETOT];
__device__ int   g_nact;
// fp16 activation planes
__device__ __align__(16) __half g_minF[NN*LDW2];
__device__ __align__(16) __half g_hidF[NN*LDW1];
__device__ __align__(16) __half g_sF  [NN*LDW1];

// =================== helpers ==================================================
__device__ __forceinline__ uint32_t smem_u32(const void* p) {
    uint32_t a;
    asm("{ .reg .u64 t; cvta.to.shared.u64 t, %1; cvt.u32.u64 %0, t; }"
        : "=r"(a) : "l"(p));
    return a;
}

__device__ __forceinline__ void ldsm4(uint32_t* r, uint32_t addr) {
    asm volatile("ldmatrix.sync.aligned.m8n8.x4.shared.b16 {%0,%1,%2,%3}, [%4];"
        : "=r"(r[0]), "=r"(r[1]), "=r"(r[2]), "=r"(r[3]) : "r"(addr));
}

__device__ __forceinline__ void mma_fp16(float* c, const uint32_t* a, const uint32_t* b) {
    asm volatile("mma.sync.aligned.m16n8k16.row.col.f32.f16.f16.f32 "
        "{%0,%1,%2,%3}, {%4,%5,%6,%7}, {%8,%9}, {%0,%1,%2,%3};"
        : "+f"(c[0]), "+f"(c[1]), "+f"(c[2]), "+f"(c[3])
        : "r"(a[0]), "r"(a[1]), "r"(a[2]), "r"(a[3]), "r"(b[0]), "r"(b[1]));
}

__device__ __forceinline__ void cpa16(uint32_t s, const void* g) {
    asm volatile("cp.async.cg.shared.global [%0], [%1], 16;" :: "r"(s), "l"(g));
}
#define CP_COMMIT asm volatile("cp.async.commit_group;" ::: "memory")
#define CP_WAIT0  asm volatile("cp.async.wait_group 0;"  ::: "memory")
#define CP_WAIT1  asm volatile("cp.async.wait_group 1;"  ::: "memory")

__device__ __forceinline__ uint32_t pack_half2(float x, float y) {
    __half2 h = __floats2half2_rn(x, y);
    return *(uint32_t*)&h;
}

__device__ __forceinline__ void store_h4(__half* p, float4 v) {
    uint2 u;
    u.x = pack_half2(v.x, v.y);
    u.y = pack_half2(v.z, v.w);
    *(uint2*)p = u;
}

__device__ __forceinline__ float4 ld_h4(const __half* p) {
    uint2 u = *(const uint2*)p;
    float2 f0 = __half22float2(*(__half2*)&u.x);
    float2 f1 = __half22float2(*(__half2*)&u.y);
    return make_float4(f0.x, f0.y, f1.x, f1.y);
}

__device__ __forceinline__ float silu(float x) {
    return x / (1.0f + __expf(-x));
}

#define LDA 136
#define ASM_ROWS 64
#define BSM_ROWS 128
#define TSZ_A (ASM_ROWS*LDA)
#define TSZ_B (BSM_ROWS*LDA)
#define GSMEM ((TSZ_A + TSZ_B)*2)    // 52224 B -> 3 CTAs/SM

// load one half-tile plane (global -> smem, cp.async)
__device__ __forceinline__ void ld_A64(uint32_t aA, const __half* g, int ld,
                                       int buf, int koff, int tid) {
#pragma unroll
    for (int it = 0; it < 2; it++) {
        int gg = tid + it*256;
        int r = gg >> 3, cc = (gg & 7) << 3;
        cpa16(aA + (uint32_t)(r*LDA + buf*64 + cc)*2, g + (size_t)r*ld + koff + cc);
    }
}
__device__ __forceinline__ void ld_B128(uint32_t aB, const __half* g, int ld,
                                        int buf, int koff, int tid) {
#pragma unroll
    for (int it = 0; it < 4; it++) {
        int gg = tid + it*256;
        int r = gg >> 3, cc = (gg & 7) << 3;
        cpa16(aB + (uint32_t)(r*LDA + buf*64 + cc)*2, g + (size_t)r*ld + koff + cc);
    }
}

// 64x128x64 fp16 MMA on one half-buffer; 8 warps (2x4), warp tile 32x32
__device__ __forceinline__ void mma_half16(uint32_t aA, uint32_t aB,
                                           int buf, int wr, int wc, int lane,
                                           float acc[2][4][4]) {
    int arow = lane & 15, acol = (lane >> 4) * 8;
    int bmat = lane >> 3;
    int brow = (bmat >> 1) * 8 + (lane & 7);
    int bcol = (bmat & 1) * 8;
    int cb = buf * 64;
#pragma unroll
    for (int ks = 0; ks < 4; ks++) {
        int k0 = cb + ks * 16;
        uint32_t a0[4], a1[4], b0[4], b1[4];
        ldsm4(a0, aA + (uint32_t)((wr*32 +      arow) * LDA + k0 + acol) * 2);
        ldsm4(a1, aA + (uint32_t)((wr*32 + 16 + arow) * LDA + k0 + acol) * 2);
        ldsm4(b0, aB + (uint32_t)((wc*32 +      brow) * LDA + k0 + bcol) * 2);
        ldsm4(b1, aB + (uint32_t)((wc*32 + 16 + brow) * LDA + k0 + bcol) * 2);
        mma_fp16(acc[0][0], a0, b0); mma_fp16(acc[0][1], a0, b0 + 2);
        mma_fp16(acc[0][2], a0, b1); mma_fp16(acc[0][3], a0, b1 + 2);
        mma_fp16(acc[1][0], a1, b0); mma_fp16(acc[1][1], a1, b0 + 2);
        mma_fp16(acc[1][2], a1, b1); mma_fp16(acc[1][3], a1, b1 + 2);
    }
}

// ====== fp16 GEMM: C = act(A @ W^T + b); CTA tile 64x128, K pipelined =======
template<int ACT, int WF32, int WSPLIT>
__global__ __launch_bounds__(256, 3)
void gemm_hp(const __half* __restrict__ A, int lda,
             const __half* __restrict__ W, int ldw,
             const float* __restrict__ bias, float* __restrict__ C,
             __half* __restrict__ CF, int ldc,
             int Nout, int Kin) {
    extern __shared__ __half sm[];
    __half* Asm = sm;
    __half* Bsm = sm + TSZ_A;
    int tid = threadIdx.x, lane = tid & 31, w = tid >> 5;
    int wr = w >> 2, wc = w & 3;
    int m0 = blockIdx.y * 64, n0 = blockIdx.x * 128;
    uint32_t aA = smem_u32(Asm), aB = smem_u32(Bsm);

    const __half* A0 = A + (size_t)m0 * lda;
    const __half* B0 = W + (size_t)n0 * ldw;

#define LOADH(buf, kh) do { int _ko = (kh)*64;        \
        ld_A64(aA, A0, lda, (buf), _ko, tid);         \
        ld_B128(aB, B0, ldw, (buf), _ko, tid);        \
        CP_COMMIT; } while (0)

    int NH = Kin >> 6;
    float acc[2][4][4] = {};
    LOADH(0, 0);
    if (NH > 1) LOADH(1, 1);
    for (int kh = 0; kh < NH; kh++) {
        if (kh + 1 < NH) { CP_WAIT1; } else { CP_WAIT0; }
        __syncthreads();
        mma_half16(aA, aB, kh & 1, wr, wc, lane, acc);
        if (kh + 2 < NH) {
            __syncthreads();
            LOADH(kh & 1, kh + 2);
        }
    }
#undef LOADH

#pragma unroll
    for (int ni = 0; ni < 4; ni++) {
        int c = wc*32 + ni*8 + (lane & 3) * 2;
        float b0 = bias[n0 + c], b1 = bias[n0 + c + 1];
#pragma unroll
        for (int mi = 0; mi < 2; mi++) {
            int r0 = m0 + wr*32 + mi*16 + (lane >> 2);
            float o0 = acc[mi][ni][0] + b0;
            float o1 = acc[mi][ni][1] + b1;
            float o2 = acc[mi][ni][2] + b0;
            float o3 = acc[mi][ni][3] + b1;
            if (ACT) {
                o0 = silu(o0); o1 = silu(o1);
                o2 = silu(o2); o3 = silu(o3);
            }
            if (WF32) {
                *(float2*)(C + (size_t)r0 * Nout + n0 + c)       = make_float2(o0, o1);
                *(float2*)(C + (size_t)(r0 + 8) * Nout + n0 + c) = make_float2(o2, o3);
            }
            if (WSPLIT) {
                *(uint32_t*)&CF[(size_t)r0*ldc + n0 + c]     = pack_half2(o0, o1);
                *(uint32_t*)&CF[(size_t)(r0+8)*ldc + n0 + c] = pack_half2(o2, o3);
            }
        }
    }
}

// ======= UV GEMM: [Uv|Vv] = (v+dv) @ [UW|VW]^T ; tile 64x128, fp16 out =====
__global__ __launch_bounds__(256, 3)
void uv_k(const __half* __restrict__ W) {
    extern __shared__ __half sm[];
    __half* Asm = sm;
    __half* Bsm = sm + TSZ_A;
    int tid = threadIdx.x, lane = tid & 31, w = tid >> 5;
    int wr = w >> 2, wc = w & 3;
    int m0 = blockIdx.y * 64, n0 = blockIdx.x * 128;
    uint32_t aA = smem_u32(Asm), aB = smem_u32(Bsm);

#pragma unroll
    for (int it = 0; it < 8; it++) {
        int gg = tid + it*256;
        int r = gg >> 4, cc = (gg & 15) << 3;
        cpa16(aB + (uint32_t)(r*LDA + cc)*2, W + (size_t)(n0 + r) * LDW1 + cc);
    }
    CP_COMMIT;
#pragma unroll
    for (int g = tid; g < 2048; g += 256) {
        int row = g >> 5, col = (g & 31) << 2;
        size_t ai = (size_t)(m0 + row) * 128 + col;
        float4 a1 = *(const float4*)(g_v + ai);
        float4 a2 = *(const float4*)(g_dv + ai);
        store_h4(Asm + row*LDA + col,
                 make_float4(a1.x+a2.x, a1.y+a2.y, a1.z+a2.z, a1.w+a2.w));
    }
    CP_WAIT0;
    __syncthreads();
    float acc[2][4][4] = {};
    mma_half16(aA, aB, 0, wr, wc, lane, acc);
    mma_half16(aA, aB, 1, wr, wc, lane, acc);

#pragma unroll
    for (int ni = 0; ni < 4; ni++) {
        int c = n0 + wc*32 + ni*8 + (lane & 3) * 2;
#pragma unroll
        for (int mi = 0; mi < 2; mi++) {
            int r0 = m0 + wr*32 + mi*16 + (lane >> 2);
            *(uint32_t*)&g_UVo[(size_t)r0 * 256 + c]
                = pack_half2(acc[mi][ni][0], acc[mi][ni][1]);
            *(uint32_t*)&g_UVo[(size_t)(r0 + 8) * 256 + c]
                = pack_half2(acc[mi][ni][2], acc[mi][ni][3]);
        }
    }
}

// ---------------- pack all weights into fp16 arena (+ reset) ----------------
__global__ void pack_all(const float* __restrict__ iW1, const float* __restrict__ iW2,
                         const float* __restrict__ mW1, const float* __restrict__ mW2,
                         const float* __restrict__ uW1, const float* __restrict__ uW2,
                         const float* __restrict__ UW,  const float* __restrict__ VW) {
    int idx = blockIdx.x * blockDim.x + threadIdx.x;
    int region = blockIdx.y;
    if (region == 0 && idx == 0) g_nact = 0;
    switch (region) {
    case 0: if (idx < 128*256) {
        int n = idx >> 8, k = idx & 255;
        g_WSF[OFF_IW1 + (size_t)n*LDW2 + k] = __float2half_rn(iW1[idx]);
    } break;
    case 1: if (idx < 128*128) {
        int n = idx >> 7, k = idx & 127;
        g_WSF[OFF_IW2 + (size_t)n*LDW1 + k] = __float2half_rn(iW2[idx]);
    } break;
    case 2: if (idx < NL*128*128) {
        int l = idx / 16384, r = idx % 16384, n = r >> 7, k = r & 127;
        g_WSF[OFF_LBASE + (size_t)l*LSTRIDE + LOFF_MW1 + (size_t)n*LDW1 + k] = __float2half_rn(mW1[idx]);
    } break;
    case 3: if (idx < NL*384*128) {
        int l = idx / 49152, r = idx % 49152, n = r >> 7, k = r & 127;
        g_WSF[OFF_LBASE + (size_t)l*LSTRIDE + LOFF_MW2 + (size_t)n*LDW1 + k] = __float2half_rn(mW2[idx]);
    } break;
    case 4: if (idx < NL*128*256) {
        int l = idx / 32768, r = idx % 32768, n = r >> 8, k = r & 255;
        g_WSF[OFF_LBASE + (size_t)l*LSTRIDE + LOFF_UW1 + (size_t)n*LDW2 + k] = __float2half_rn(uW1[idx]);
    } break;
    case 5: if (idx < NL*384*128) {
        int l = idx / 49152, r = idx % 49152, n = r >> 7, k = r & 127;
        g_WSF[OFF_LBASE + (size_t)l*LSTRIDE + LOFF_UW2 + (size_t)n*LDW1 + k] = __float2half_rn(uW2[idx]);
    } break;
    case 6: if (idx < NL*128*128) {
        int l = idx / 16384, r = idx % 16384, n = r >> 7, k = r & 127;
        g_WSF[OFF_LBASE + (size_t)l*LSTRIDE + LOFF_UVW + (size_t)n*LDW1 + k] = __float2half_rn(UW[idx]);
    } break;
    case 7: if (idx < NL*128*128) {
        int l = idx / 16384, r = idx % 16384, n = r >> 7, k = r & 127;
        g_WSF[OFF_LBASE + (size_t)l*LSTRIDE + LOFF_UVW + (size_t)(128+n)*LDW1 + k] = __float2half_rn(VW[idx]);
    } break;
    }
}

// ---------------- misc kernels ------------------------------------------------
__global__ void geom_k(const float* __restrict__ xyz, const float* __restrict__ cell,
                       const int* __restrict__ aedges, const float* __restrict__ edisp) {
    int e = blockIdx.x * blockDim.x + threadIdx.x;
    if (e >= ETOT) return;
    int b = e / EPER;
    int snd = aedges[2*e]   + b * NPER;
    int rcv = aedges[2*e+1] + b * NPER;
    const float* cb = cell + b * 9;
    float c0 = edisp[3*e], c1 = edisp[3*e+1], c2 = edisp[3*e+2];
    float dx[3];
#pragma unroll
    for (int d = 0; d < 3; d++) {
        float disp = c0 * cb[d] + c1 * cb[3+d] + c2 * cb[6+d];
        dx[d] = xyz[3*rcv+d] - (xyz[3*snd+d] + disp);
    }
    float dist = sqrtf(dx[0]*dx[0] + dx[1]*dx[1] + dx[2]*dx[2]);
    if (dist < CUTF) {
        int p = atomicAdd(&g_nact, 1);
        g_send[p] = snd; g_recv[p] = rcv;
        float inv  = 1.0f / dist;
        float invm = 1.0f / fmaxf(dist, 1e-12f);
#pragma unroll
        for (int k = 0; k < KF; k++)
            g_es[p*KF+k] = sinf(dist * (float)(k+1) * (PIF/CUTF)) * inv;
        g_cut[p] = 0.5f * (cosf(PIF * dist / CUTF) + 1.0f);
        g_dir[3*p]   = dx[0]*invm;
        g_dir[3*p+1] = dx[1]*invm;
        g_dir[3*p+2] = dx[2]*invm;
    }
}

// h = [atom_emb[node], V*potW + potb] -> fp16 g_min
__global__ void init_h_k(const int* __restrict__ nodes, const float* __restrict__ Vflat,
                         const float* __restrict__ emb, const float* __restrict__ potW,
                         const float* __restrict__ potb) {
    int idx = blockIdx.x * blockDim.x + threadIdx.x;
    if (idx >= NN*32) return;
    int n = idx >> 5, j = (idx & 31) << 2;
    float4 ev = *(const float4*)(emb + (size_t)nodes[n]*F + j);
    store_h4(g_minF + (size_t)n*LDW2 + j, ev);
    float vf = Vflat[n];
    float4 pw = *(const float4*)(potW + j);
    float4 pb = *(const float4*)(potb + j);
    float4 pv = make_float4(vf*pw.x+pb.x, vf*pw.y+pb.y, vf*pw.z+pb.z, vf*pw.w+pb.w);
    store_h4(g_minF + (size_t)n*LDW2 + 128 + j, pv);
}

__global__ void init_v_k(const float* __restrict__ Eflat, const float* __restrict__ vecw) {
    int idx = blockIdx.x * blockDim.x + threadIdx.x;
    if (idx >= NN*3*32) return;
    int r = idx >> 5, j = (idx & 31) << 2;
    float e = Eflat[r];
    float4 w = *(const float4*)(vecw + j);
    *(float4*)(g_v + (size_t)r*F + j) = make_float4(e*w.x, e*w.y, e*w.z, e*w.w);
}

#define EPB 32
__global__ __launch_bounds__(128)
void edge_k(const float* __restrict__ fW, const float* __restrict__ fb) {
    int nact = g_nact;
    int e0 = blockIdx.x * EPB;
    if (e0 >= nact) return;
    __shared__ float sW[384*21];
    __shared__ float sb[384];
    for (int i = threadIdx.x; i < 384*KF; i += 128)
        sW[(i/KF)*21 + (i%KF)] = fW[i];
    for (int i = threadIdx.x; i < 384; i += 128) sb[i] = fb[i];
    __syncthreads();
    int j = threadIdx.x;
    int e1 = min(e0 + EPB, nact);
    for (int e = e0; e < e1; e++) {
        int snd = g_send[e], rcv = g_recv[e];
        float cutv = g_cut[e];
        float esr[KF];
#pragma unroll
        for (int k = 0; k < KF; k++) esr[k] = g_es[e*KF+k];
        float fw0 = sb[j], fw1 = sb[j+128], fw2 = sb[j+256];
#pragma unroll
        for (int k = 0; k < KF; k++) {
            fw0 += sW[j*21+k]       * esr[k];
            fw1 += sW[(j+128)*21+k] * esr[k];
            fw2 += sW[(j+256)*21+k] * esr[k];
        }
        const __half* sop = g_soF + (size_t)snd * 384;
        float gsv = fw0 * cutv * __half2float(sop[j]);
        float gev = fw1 * cutv * __half2float(sop[j+128]);
        float gns = fw2 * cutv * __half2float(sop[j+256]);
        atomicAdd(&g_ds[rcv*F + j], g_s[snd*F + j] * gns);
        float d0 = g_dir[3*e], d1 = g_dir[3*e+1], d2 = g_dir[3*e+2];
        atomicAdd(&g_dv[(rcv*3+0)*F + j], g_v[(snd*3+0)*F + j]*gsv + gev*d0);
        atomicAdd(&g_dv[(rcv*3+1)*F + j], g_v[(snd*3+1)*F + j]*gsv + gev*d1);
        atomicAdd(&g_dv[(rcv*3+2)*F + j], g_v[(snd*3+2)*F + j]*gsv + gev*d2);
    }
}

// s += ds; dot; fp16 g_min = [s, Vn]
__global__ void prep_k() {
    int idx = blockIdx.x * blockDim.x + threadIdx.x;
    if (idx >= NN*32) return;
    int n = idx >> 5, j = (idx & 31) << 2;
    size_t si = (size_t)n*F + j;
    float4 s4 = *(const float4*)(g_s + si);
    float4 d4 = *(const float4*)(g_ds + si);
    float4 sv = make_float4(s4.x+d4.x, s4.y+d4.y, s4.z+d4.z, s4.w+d4.w);
    *(float4*)(g_s + si) = sv;
    *(float4*)(g_ds + si) = make_float4(0.f, 0.f, 0.f, 0.f);
    float4 u0 = ld_h4(g_UVo + (size_t)(n*3+0)*256 + j);
    float4 u1 = ld_h4(g_UVo + (size_t)(n*3+1)*256 + j);
    float4 u2 = ld_h4(g_UVo + (size_t)(n*3+2)*256 + j);
    float4 w0 = ld_h4(g_UVo + (size_t)(n*3+0)*256 + 128 + j);
    float4 w1 = ld_h4(g_UVo + (size_t)(n*3+1)*256 + 128 + j);
    float4 w2 = ld_h4(g_UVo + (size_t)(n*3+2)*256 + 128 + j);
    *(float4*)(g_dot + si) = make_float4(u0.x*w0.x + u1.x*w1.x + u2.x*w2.x,
                                         u0.y*w0.y + u1.y*w1.y + u2.y*w2.y,
                                         u0.z*w0.z + u1.z*w1.z + u2.z*w2.z,
                                         u0.w*w0.w + u1.w*w1.w + u2.w*w2.w);
    store_h4(g_minF + (size_t)n*LDW2 + j, sv);
    float4 vn = make_float4(sqrtf(w0.x*w0.x + w1.x*w1.x + w2.x*w2.x),
                            sqrtf(w0.y*w0.y + w1.y*w1.y + w2.y*w2.y),
                            sqrtf(w0.z*w0.z + w1.z*w1.z + w2.z*w2.z),
                            sqrtf(w0.w*w0.w + w1.w*w1.w + w2.w*w2.w));
    store_h4(g_minF + (size_t)n*LDW2 + 128 + j, vn);
}

// s += a_ss + a_sv*dot (also fp16); v = v + dv + a_vv*Uv ; dv=0 ; output
__global__ void final_k(float* __restrict__ out, int l) {
    int idx = blockIdx.x * blockDim.x + threadIdx.x;
    if (idx >= NN*32) return;
    int n = idx >> 5, j = (idx & 31) << 2;
    size_t si = (size_t)n*F + j;
    float4 ass = ld_h4(g_mF + (size_t)n*384 + j);
    float4 asv = ld_h4(g_mF + (size_t)n*384 + 128 + j);
    float4 avv = ld_h4(g_mF + (size_t)n*384 + 256 + j);
    float4 dt  = *(const float4*)(g_dot + si);
    float4 s4  = *(const float4*)(g_s + si);
    float4 sv = make_float4(s4.x + ass.x + asv.x*dt.x,
                            s4.y + ass.y + asv.y*dt.y,
                            s4.z + ass.z + asv.z*dt.z,
                            s4.w + ass.w + asv.w*dt.w);
    *(float4*)(g_s + si) = sv;
    store_h4(g_sF + (size_t)n*LDW1 + j, sv);
    size_t ob = ((size_t)(l*NN + n) * 4) * F + j;
    *(float4*)(out + ob) = sv;
    float4 z = make_float4(0.f, 0.f, 0.f, 0.f);
#pragma unroll
    for (int d = 0; d < 3; d++) {
        size_t vi = (size_t)(n*3 + d)*F + j;
        float4 uv = ld_h4(g_UVo + (size_t)(n*3 + d)*256 + j);
        float4 v4 = *(const float4*)(g_v + vi);
        float4 dv = *(const float4*)(g_dv + vi);
        float4 vv = make_float4(v4.x + dv.x + avv.x*uv.x,
                                v4.y + dv.y + avv.y*uv.y,
                                v4.z + dv.z + avv.z*uv.z,
                                v4.w + dv.w + avv.w*uv.w);
        *(float4*)(g_v + vi) = vv;
        *(float4*)(g_dv + vi) = z;
        *(float4*)(out + ob + (size_t)(d+1)*F) = vv;
    }
}

// ---------------- host launcher ---------------------------------------------
static float* sym(const void* s) { void* p = nullptr; cudaGetSymbolAddress(&p, s); return (float*)p; }

extern "C" void kernel_launch(void* const* d_in, const int* in_sizes, int n_in,
                              void* d_out, int out_size) {
    (void)in_sizes; (void)n_in; (void)out_size;
    const float* atom_xyz = (const float*)d_in[0];
    const float* cell     = (const float*)d_in[1];
    const int*   nodes    = (const int*)  d_in[2];
    const int*   aedges   = (const int*)  d_in[3];
    const float* edisp    = (const float*)d_in[4];
    const float* Vflat    = (const float*)d_in[5];
    const float* Eflat    = (const float*)d_in[6];
    const float* emb      = (const float*)d_in[7];
    const float* potW     = (const float*)d_in[8];
    const float* potb     = (const float*)d_in[9];
    const float* iW1      = (const float*)d_in[10];
    const float* ib1      = (const float*)d_in[11];
    const float* iW2      = (const float*)d_in[12];
    const float* ib2      = (const float*)d_in[13];
    const float* vecw     = (const float*)d_in[14];
    const float* filtW    = (const float*)d_in[15];
    const float* filtb    = (const float*)d_in[16];
    const float* mW1      = (const float*)d_in[17];
    const float* mb1      = (const float*)d_in[18];
    const float* mW2      = (const float*)d_in[19];
    const float* mb2      = (const float*)d_in[20];
    const float* UW       = (const float*)d_in[21];
    const float* VW       = (const float*)d_in[22];
    const float* uW1      = (const float*)d_in[23];
    const float* ub1      = (const float*)d_in[24];
    const float* uW2      = (const float*)d_in[25];
    const float* ub2      = (const float*)d_in[26];
    float* out = (float*)d_out;

    float* ps   = sym(g_s);
    __half* psoF = (__half*)sym(g_soF);
    __half* pmF  = (__half*)sym(g_mF);
    __half* pWSF  = (__half*)sym(g_WSF);
    __half* pminF = (__half*)sym(g_minF);
    __half* phidF = (__half*)sym(g_hidF);
    __half* psF   = (__half*)sym(g_sF);

    cudaFuncSetAttribute((const void*)gemm_hp<1,0,1>,
                         cudaFuncAttributeMaxDynamicSharedMemorySize, GSMEM);
    cudaFuncSetAttribute((const void*)gemm_hp<0,1,1>,
                         cudaFuncAttributeMaxDynamicSharedMemorySize, GSMEM);
    cudaFuncSetAttribute((const void*)gemm_hp<0,0,1>,
                         cudaFuncAttributeMaxDynamicSharedMemorySize, GSMEM);
    cudaFuncSetAttribute((const void*)uv_k,
                         cudaFuncAttributeMaxDynamicSharedMemorySize, GSMEM);

    const int T = 256;
    const int GEO_B  = (ETOT + T - 1) / T;
    const int NF4_B  = (NN*32 + T - 1) / T;
    const int N3F4_B = (NN*3*32 + T - 1) / T;
    const int MB  = NN / 64;       // 256 m-tiles
    const int MB3 = 3*NN / 64;     // 768 m-tiles

    // 1: pack (includes nact reset)  2: geom  3: init_h  4: gemm (profiled)
    pack_all<<<dim3(576, 8), T>>>(iW1, iW2, mW1, mW2, uW1, uW2, UW, VW);
    geom_k<<<GEO_B, T>>>(atom_xyz, cell, aedges, edisp);
    init_h_k<<<NF4_B, T>>>(nodes, Vflat, emb, potW, potb);
    // init1: hid = silu(min @ iW1^T + ib1)
    gemm_hp<1,0,1><<<dim3(1, MB), T, GSMEM>>>(pminF, LDW2,
        pWSF + OFF_IW1, LDW2, ib1, nullptr, phidF, LDW1, F, 2*F);
    // init2: s = hid @ iW2^T + ib2   (f32 + fp16 out)
    gemm_hp<0,1,1><<<dim3(1, MB), T, GSMEM>>>(phidF, LDW1,
        pWSF + OFF_IW2, LDW1, ib2, ps, psF, LDW1, F, F);
    init_v_k<<<N3F4_B, T>>>(Eflat, vecw);

    for (int l = 0; l < NL; l++) {
        size_t lb = OFF_LBASE + (size_t)l*LSTRIDE;
        // msg1: hid = silu(s @ mW1^T + mb1)
        gemm_hp<1,0,1><<<dim3(1, MB), T, GSMEM>>>(psF, LDW1,
            pWSF + lb + LOFF_MW1, LDW1, mb1 + l*F, nullptr, phidF, LDW1, F, F);
        // msg2: so = hid @ mW2^T + mb2   (fp16 out)
        gemm_hp<0,0,1><<<dim3(3, MB), T, GSMEM>>>(phidF, LDW1,
            pWSF + lb + LOFF_MW2, LDW1, mb2 + l*3*F, nullptr, psoF, 384, 3*F, F);
        edge_k<<<ETOT/EPB, 128>>>(filtW + (size_t)l*3*F*KF, filtb + (size_t)l*3*F);
        uv_k<<<dim3(2, MB3), T, GSMEM>>>(pWSF + lb + LOFF_UVW);
        prep_k<<<NF4_B, T>>>();
        // upd1: hid = silu(min @ uW1^T + ub1)
        gemm_hp<1,0,1><<<dim3(1, MB), T, GSMEM>>>(pminF, LDW2,
            pWSF + lb + LOFF_UW1, LDW2, ub1 + l*F, nullptr, phidF, LDW1, F, 2*F);
        // upd2: m = hid @ uW2^T + ub2   (fp16 out)
        gemm_hp<0,0,1><<<dim3(3, MB), T, GSMEM>>>(phidF, LDW1,
            pWSF + lb + LOFF_UW2, LDW1, ub2 + l*3*F, nullptr, pmF, 384, 3*F, F);
        final_k<<<NF4_B, T>>>(out, l);
    }
}

// round 16
// speedup vs baseline: 1.1010x; 1.1010x over previous
#include <cuda_runtime.h>
#include <cuda_fp16.h>
#include <math.h>
#include <stdint.h>

#define NB 4
#define NPER 4096
#define EPER 49152
#define NN (NB*NPER)        // 16384 nodes
#define ETOT (NB*EPER)      // 196608 edges
#define F 128
#define KF 20
#define NL 3
#define CUTF 5.0f
#define PIF 3.14159265358979323846f

#define LDW1 136            // row stride (elems) for K=128 planes
#define LDW2 264            // row stride for K=256 planes

// ------------- fp16 weight arena (packed once per launch) -------------------
#define OFF_IW1 0
#define SZ_IW1 (128*LDW2)
#define OFF_IW2 (OFF_IW1 + SZ_IW1)
#define SZ_IW2 (128*LDW1)
#define OFF_LBASE (OFF_IW2 + SZ_IW2)
#define LOFF_MW1 0
#define LOFF_MW2 (128*LDW1)
#define LOFF_UW1 (LOFF_MW2 + 384*LDW1)
#define LOFF_UW2 (LOFF_UW1 + 128*LDW2)
#define LOFF_UVW (LOFF_UW2 + 384*LDW1)
#define LSTRIDE  (LOFF_UVW + 256*LDW1)
#define WARENA   (OFF_LBASE + NL*LSTRIDE)

__device__ __align__(16) __half g_WSF[WARENA];

// ---------------- scratch -----------------------------------------------------
__device__ __align__(16) float g_s  [NN*F];
__device__ __align__(16) float g_v  [NN*3*F];
__device__ __align__(16) float g_ds [NN*F];
__device__ __align__(16) float g_dv [NN*3*F];
__device__ __align__(16) __half g_soF[NN*3*F];     // fp16 message-MLP output
__device__ __align__(16) __half g_mF [NN*3*F];     // fp16 update-MLP output
__device__ __align__(16) __half g_UVo[NN*3*256];   // fp16 Uv|Vv
__device__ __align__(16) float g_dot[NN*F];
__device__ __align__(16) float g_es [ETOT*KF];
__device__ float g_cut[ETOT];
__device__ float g_dir[ETOT*3];
__device__ int   g_send[ETOT];
__device__ int   g_recv[ETOT];
__device__ int   g_nact;
// fp16 activation planes
__device__ __align__(16) __half g_minF[NN*LDW2];
__device__ __align__(16) __half g_hidF[NN*LDW1];
__device__ __align__(16) __half g_sF  [NN*LDW1];

// =================== helpers ==================================================
__device__ __forceinline__ uint32_t smem_u32(const void* p) {
    uint32_t a;
    asm("{ .reg .u64 t; cvta.to.shared.u64 t, %1; cvt.u32.u64 %0, t; }"
        : "=r"(a) : "l"(p));
    return a;
}

__device__ __forceinline__ void ldsm4(uint32_t* r, uint32_t addr) {
    asm volatile("ldmatrix.sync.aligned.m8n8.x4.shared.b16 {%0,%1,%2,%3}, [%4];"
        : "=r"(r[0]), "=r"(r[1]), "=r"(r[2]), "=r"(r[3]) : "r"(addr));
}

__device__ __forceinline__ void mma_fp16(float* c, const uint32_t* a, const uint32_t* b) {
    asm volatile("mma.sync.aligned.m16n8k16.row.col.f32.f16.f16.f32 "
        "{%0,%1,%2,%3}, {%4,%5,%6,%7}, {%8,%9}, {%0,%1,%2,%3};"
        : "+f"(c[0]), "+f"(c[1]), "+f"(c[2]), "+f"(c[3])
        : "r"(a[0]), "r"(a[1]), "r"(a[2]), "r"(a[3]), "r"(b[0]), "r"(b[1]));
}

__device__ __forceinline__ void cpa16(uint32_t s, const void* g) {
    asm volatile("cp.async.cg.shared.global [%0], [%1], 16;" :: "r"(s), "l"(g));
}
#define CP_COMMIT asm volatile("cp.async.commit_group;" ::: "memory")
#define CP_WAIT0  asm volatile("cp.async.wait_group 0;"  ::: "memory")
#define CP_WAIT1  asm volatile("cp.async.wait_group 1;"  ::: "memory")

__device__ __forceinline__ uint32_t pack_half2(float x, float y) {
    __half2 h = __floats2half2_rn(x, y);
    return *(uint32_t*)&h;
}

__device__ __forceinline__ void store_h4(__half* p, float4 v) {
    uint2 u;
    u.x = pack_half2(v.x, v.y);
    u.y = pack_half2(v.z, v.w);
    *(uint2*)p = u;
}

__device__ __forceinline__ float4 ld_h4(const __half* p) {
    uint2 u = *(const uint2*)p;
    float2 f0 = __half22float2(*(__half2*)&u.x);
    float2 f1 = __half22float2(*(__half2*)&u.y);
    return make_float4(f0.x, f0.y, f1.x, f1.y);
}

__device__ __forceinline__ float silu(float x) {
    return x / (1.0f + __expf(-x));
}

#define LDA 136
#define ASM_ROWS 64
#define BSM_ROWS 128
#define TSZ_A (ASM_ROWS*LDA)
#define TSZ_B (BSM_ROWS*LDA)
#define GSMEM ((TSZ_A + TSZ_B)*2)    // 52224 B -> 3 CTAs/SM

// load one half-tile plane (global -> smem, cp.async)
__device__ __forceinline__ void ld_A64(uint32_t aA, const __half* g, int ld,
                                       int buf, int koff, int tid) {
#pragma unroll
    for (int it = 0; it < 2; it++) {
        int gg = tid + it*256;
        int r = gg >> 3, cc = (gg & 7) << 3;
        cpa16(aA + (uint32_t)(r*LDA + buf*64 + cc)*2, g + (size_t)r*ld + koff + cc);
    }
}
__device__ __forceinline__ void ld_B128(uint32_t aB, const __half* g, int ld,
                                        int buf, int koff, int tid) {
#pragma unroll
    for (int it = 0; it < 4; it++) {
        int gg = tid + it*256;
        int r = gg >> 3, cc = (gg & 7) << 3;
        cpa16(aB + (uint32_t)(r*LDA + buf*64 + cc)*2, g + (size_t)r*ld + koff + cc);
    }
}

// 64x128x64 fp16 MMA on one half-buffer; 8 warps (2x4), warp tile 32x32
__device__ __forceinline__ void mma_half16(uint32_t aA, uint32_t aB,
                                           int buf, int wr, int wc, int lane,
                                           float acc[2][4][4]) {
    int arow = lane & 15, acol = (lane >> 4) * 8;
    int bmat = lane >> 3;
    int brow = (bmat >> 1) * 8 + (lane & 7);
    int bcol = (bmat & 1) * 8;
    int cb = buf * 64;
#pragma unroll
    for (int ks = 0; ks < 4; ks++) {
        int k0 = cb + ks * 16;
        uint32_t a0[4], a1[4], b0[4], b1[4];
        ldsm4(a0, aA + (uint32_t)((wr*32 +      arow) * LDA + k0 + acol) * 2);
        ldsm4(a1, aA + (uint32_t)((wr*32 + 16 + arow) * LDA + k0 + acol) * 2);
        ldsm4(b0, aB + (uint32_t)((wc*32 +      brow) * LDA + k0 + bcol) * 2);
        ldsm4(b1, aB + (uint32_t)((wc*32 + 16 + brow) * LDA + k0 + bcol) * 2);
        mma_fp16(acc[0][0], a0, b0); mma_fp16(acc[0][1], a0, b0 + 2);
        mma_fp16(acc[0][2], a0, b1); mma_fp16(acc[0][3], a0, b1 + 2);
        mma_fp16(acc[1][0], a1, b0); mma_fp16(acc[1][1], a1, b0 + 2);
        mma_fp16(acc[1][2], a1, b1); mma_fp16(acc[1][3], a1, b1 + 2);
    }
}

// ====== fp16 GEMM: C = act(A @ W^T + b); CTA tile 64x128, K pipelined =======
template<int ACT, int WF32, int WSPLIT>
__global__ __launch_bounds__(256, 3)
void gemm_hp(const __half* __restrict__ A, int lda,
             const __half* __restrict__ W, int ldw,
             const float* __restrict__ bias, float* __restrict__ C,
             __half* __restrict__ CF, int ldc,
             int Nout, int Kin) {
    extern __shared__ __half sm[];
    __half* Asm = sm;
    __half* Bsm = sm + TSZ_A;
    int tid = threadIdx.x, lane = tid & 31, w = tid >> 5;
    int wr = w >> 2, wc = w & 3;
    int m0 = blockIdx.y * 64, n0 = blockIdx.x * 128;
    uint32_t aA = smem_u32(Asm), aB = smem_u32(Bsm);

    const __half* A0 = A + (size_t)m0 * lda;
    const __half* B0 = W + (size_t)n0 * ldw;

#define LOADH(buf, kh) do { int _ko = (kh)*64;        \
        ld_A64(aA, A0, lda, (buf), _ko, tid);         \
        ld_B128(aB, B0, ldw, (buf), _ko, tid);        \
        CP_COMMIT; } while (0)

    int NH = Kin >> 6;
    float acc[2][4][4] = {};
    LOADH(0, 0);
    if (NH > 1) LOADH(1, 1);
    for (int kh = 0; kh < NH; kh++) {
        if (kh + 1 < NH) { CP_WAIT1; } else { CP_WAIT0; }
        __syncthreads();
        mma_half16(aA, aB, kh & 1, wr, wc, lane, acc);
        if (kh + 2 < NH) {
            __syncthreads();
            LOADH(kh & 1, kh + 2);
        }
    }
#undef LOADH

#pragma unroll
    for (int ni = 0; ni < 4; ni++) {
        int c = wc*32 + ni*8 + (lane & 3) * 2;
        float b0 = bias[n0 + c], b1 = bias[n0 + c + 1];
#pragma unroll
        for (int mi = 0; mi < 2; mi++) {
            int r0 = m0 + wr*32 + mi*16 + (lane >> 2);
            float o0 = acc[mi][ni][0] + b0;
            float o1 = acc[mi][ni][1] + b1;
            float o2 = acc[mi][ni][2] + b0;
            float o3 = acc[mi][ni][3] + b1;
            if (ACT) {
                o0 = silu(o0); o1 = silu(o1);
                o2 = silu(o2); o3 = silu(o3);
            }
            if (WF32) {
                *(float2*)(C + (size_t)r0 * Nout + n0 + c)       = make_float2(o0, o1);
                *(float2*)(C + (size_t)(r0 + 8) * Nout + n0 + c) = make_float2(o2, o3);
            }
            if (WSPLIT) {
                *(uint32_t*)&CF[(size_t)r0*ldc + n0 + c]     = pack_half2(o0, o1);
                *(uint32_t*)&CF[(size_t)(r0+8)*ldc + n0 + c] = pack_half2(o2, o3);
            }
        }
    }
}

// ======= UV GEMM: [Uv|Vv] = (v+dv) @ [UW|VW]^T ; tile 64x128, fp16 out =====
__global__ __launch_bounds__(256, 3)
void uv_k(const __half* __restrict__ W) {
    extern __shared__ __half sm[];
    __half* Asm = sm;
    __half* Bsm = sm + TSZ_A;
    int tid = threadIdx.x, lane = tid & 31, w = tid >> 5;
    int wr = w >> 2, wc = w & 3;
    int m0 = blockIdx.y * 64, n0 = blockIdx.x * 128;
    uint32_t aA = smem_u32(Asm), aB = smem_u32(Bsm);

#pragma unroll
    for (int it = 0; it < 8; it++) {
        int gg = tid + it*256;
        int r = gg >> 4, cc = (gg & 15) << 3;
        cpa16(aB + (uint32_t)(r*LDA + cc)*2, W + (size_t)(n0 + r) * LDW1 + cc);
    }
    CP_COMMIT;
#pragma unroll
    for (int g = tid; g < 2048; g += 256) {
        int row = g >> 5, col = (g & 31) << 2;
        size_t ai = (size_t)(m0 + row) * 128 + col;
        float4 a1 = *(const float4*)(g_v + ai);
        float4 a2 = *(const float4*)(g_dv + ai);
        store_h4(Asm + row*LDA + col,
                 make_float4(a1.x+a2.x, a1.y+a2.y, a1.z+a2.z, a1.w+a2.w));
    }
    CP_WAIT0;
    __syncthreads();
    float acc[2][4][4] = {};
    mma_half16(aA, aB, 0, wr, wc, lane, acc);
    mma_half16(aA, aB, 1, wr, wc, lane, acc);

#pragma unroll
    for (int ni = 0; ni < 4; ni++) {
        int c = n0 + wc*32 + ni*8 + (lane & 3) * 2;
#pragma unroll
        for (int mi = 0; mi < 2; mi++) {
            int r0 = m0 + wr*32 + mi*16 + (lane >> 2);
            *(uint32_t*)&g_UVo[(size_t)r0 * 256 + c]
                = pack_half2(acc[mi][ni][0], acc[mi][ni][1]);
            *(uint32_t*)&g_UVo[(size_t)(r0 + 8) * 256 + c]
                = pack_half2(acc[mi][ni][2], acc[mi][ni][3]);
        }
    }
}

// ---------------- pack all weights into fp16 arena (+ reset) ----------------
__global__ void pack_all(const float* __restrict__ iW1, const float* __restrict__ iW2,
                         const float* __restrict__ mW1, const float* __restrict__ mW2,
                         const float* __restrict__ uW1, const float* __restrict__ uW2,
                         const float* __restrict__ UW,  const float* __restrict__ VW) {
    int idx = blockIdx.x * blockDim.x + threadIdx.x;
    int region = blockIdx.y;
    if (region == 0 && idx == 0) g_nact = 0;
    switch (region) {
    case 0: if (idx < 128*256) {
        int n = idx >> 8, k = idx & 255;
        g_WSF[OFF_IW1 + (size_t)n*LDW2 + k] = __float2half_rn(iW1[idx]);
    } break;
    case 1: if (idx < 128*128) {
        int n = idx >> 7, k = idx & 127;
        g_WSF[OFF_IW2 + (size_t)n*LDW1 + k] = __float2half_rn(iW2[idx]);
    } break;
    case 2: if (idx < NL*128*128) {
        int l = idx / 16384, r = idx % 16384, n = r >> 7, k = r & 127;
        g_WSF[OFF_LBASE + (size_t)l*LSTRIDE + LOFF_MW1 + (size_t)n*LDW1 + k] = __float2half_rn(mW1[idx]);
    } break;
    case 3: if (idx < NL*384*128) {
        int l = idx / 49152, r = idx % 49152, n = r >> 7, k = r & 127;
        g_WSF[OFF_LBASE + (size_t)l*LSTRIDE + LOFF_MW2 + (size_t)n*LDW1 + k] = __float2half_rn(mW2[idx]);
    } break;
    case 4: if (idx < NL*128*256) {
        int l = idx / 32768, r = idx % 32768, n = r >> 8, k = r & 255;
        g_WSF[OFF_LBASE + (size_t)l*LSTRIDE + LOFF_UW1 + (size_t)n*LDW2 + k] = __float2half_rn(uW1[idx]);
    } break;
    case 5: if (idx < NL*384*128) {
        int l = idx / 49152, r = idx % 49152, n = r >> 7, k = r & 127;
        g_WSF[OFF_LBASE + (size_t)l*LSTRIDE + LOFF_UW2 + (size_t)n*LDW1 + k] = __float2half_rn(uW2[idx]);
    } break;
    case 6: if (idx < NL*128*128) {
        int l = idx / 16384, r = idx % 16384, n = r >> 7, k = r & 127;
        g_WSF[OFF_LBASE + (size_t)l*LSTRIDE + LOFF_UVW + (size_t)n*LDW1 + k] = __float2half_rn(UW[idx]);
    } break;
    case 7: if (idx < NL*128*128) {
        int l = idx / 16384, r = idx % 16384, n = r >> 7, k = r & 127;
        g_WSF[OFF_LBASE + (size_t)l*LSTRIDE + LOFF_UVW + (size_t)(128+n)*LDW1 + k] = __float2half_rn(VW[idx]);
    } break;
    }
}

// ---------------- misc kernels ------------------------------------------------
__global__ void geom_k(const float* __restrict__ xyz, const float* __restrict__ cell,
                       const int* __restrict__ aedges, const float* __restrict__ edisp) {
    int e = blockIdx.x * blockDim.x + threadIdx.x;
    if (e >= ETOT) return;
    int b = e / EPER;
    int snd = aedges[2*e]   + b * NPER;
    int rcv = aedges[2*e+1] + b * NPER;
    const float* cb = cell + b * 9;
    float c0 = edisp[3*e], c1 = edisp[3*e+1], c2 = edisp[3*e+2];
    float dx[3];
#pragma unroll
    for (int d = 0; d < 3; d++) {
        float disp = c0 * cb[d] + c1 * cb[3+d] + c2 * cb[6+d];
        dx[d] = xyz[3*rcv+d] - (xyz[3*snd+d] + disp);
    }
    float dist = sqrtf(dx[0]*dx[0] + dx[1]*dx[1] + dx[2]*dx[2]);
    if (dist < CUTF) {
        int p = atomicAdd(&g_nact, 1);
        g_send[p] = snd; g_recv[p] = rcv;
        float inv  = 1.0f / dist;
        float invm = 1.0f / fmaxf(dist, 1e-12f);
#pragma unroll
        for (int k = 0; k < KF; k++)
            g_es[p*KF+k] = sinf(dist * (float)(k+1) * (PIF/CUTF)) * inv;
        g_cut[p] = 0.5f * (cosf(PIF * dist / CUTF) + 1.0f);
        g_dir[3*p]   = dx[0]*invm;
        g_dir[3*p+1] = dx[1]*invm;
        g_dir[3*p+2] = dx[2]*invm;
    }
}

// h = [atom_emb[node], V*potW + potb] -> fp16 g_min
__global__ void init_h_k(const int* __restrict__ nodes, const float* __restrict__ Vflat,
                         const float* __restrict__ emb, const float* __restrict__ potW,
                         const float* __restrict__ potb) {
    int idx = blockIdx.x * blockDim.x + threadIdx.x;
    if (idx >= NN*32) return;
    int n = idx >> 5, j = (idx & 31) << 2;
    float4 ev = *(const float4*)(emb + (size_t)nodes[n]*F + j);
    store_h4(g_minF + (size_t)n*LDW2 + j, ev);
    float vf = Vflat[n];
    float4 pw = *(const float4*)(potW + j);
    float4 pb = *(const float4*)(potb + j);
    float4 pv = make_float4(vf*pw.x+pb.x, vf*pw.y+pb.y, vf*pw.z+pb.z, vf*pw.w+pb.w);
    store_h4(g_minF + (size_t)n*LDW2 + 128 + j, pv);
}

__global__ void init_v_k(const float* __restrict__ Eflat, const float* __restrict__ vecw) {
    int idx = blockIdx.x * blockDim.x + threadIdx.x;
    if (idx >= NN*3*32) return;
    int r = idx >> 5, j = (idx & 31) << 2;
    float e = Eflat[r];
    float4 w = *(const float4*)(vecw + j);
    *(float4*)(g_v + (size_t)r*F + j) = make_float4(e*w.x, e*w.y, e*w.z, e*w.w);
}

// one edge per block-iteration; per-thread filter rows held in registers.
#define EGRID 4096
__global__ __launch_bounds__(128)
void edge_k(const float* __restrict__ fW, const float* __restrict__ fb) {
    int nact = g_nact;
    if (blockIdx.x >= nact) return;
    int j = threadIdx.x;
    float fb0 = fb[j], fb1 = fb[j+128], fb2 = fb[j+256];
    float w0[KF], w1[KF], w2[KF];
    const float* w0p = fW + (size_t)j*KF;
    const float* w1p = fW + (size_t)(j+128)*KF;
    const float* w2p = fW + (size_t)(j+256)*KF;
#pragma unroll
    for (int k = 0; k < KF; k++) { w0[k] = w0p[k]; w1[k] = w1p[k]; w2[k] = w2p[k]; }

    for (int e = blockIdx.x; e < nact; e += EGRID) {
        int snd = g_send[e], rcv = g_recv[e];
        float cutv = g_cut[e];
        float esr[KF];
#pragma unroll
        for (int k = 0; k < KF; k++) esr[k] = g_es[e*KF+k];
        float fw0 = fb0, fw1 = fb1, fw2 = fb2;
#pragma unroll
        for (int k = 0; k < KF; k++) {
            fw0 += w0[k] * esr[k];
            fw1 += w1[k] * esr[k];
            fw2 += w2[k] * esr[k];
        }
        const __half* sop = g_soF + (size_t)snd * 384;
        float gsv = fw0 * cutv * __half2float(sop[j]);
        float gev = fw1 * cutv * __half2float(sop[j+128]);
        float gns = fw2 * cutv * __half2float(sop[j+256]);
        atomicAdd(&g_ds[rcv*F + j], g_s[snd*F + j] * gns);
        float d0 = g_dir[3*e], d1 = g_dir[3*e+1], d2 = g_dir[3*e+2];
        atomicAdd(&g_dv[(rcv*3+0)*F + j], g_v[(snd*3+0)*F + j]*gsv + gev*d0);
        atomicAdd(&g_dv[(rcv*3+1)*F + j], g_v[(snd*3+1)*F + j]*gsv + gev*d1);
        atomicAdd(&g_dv[(rcv*3+2)*F + j], g_v[(snd*3+2)*F + j]*gsv + gev*d2);
    }
}

// s += ds; dot; fp16 g_min = [s, Vn]
__global__ void prep_k() {
    int idx = blockIdx.x * blockDim.x + threadIdx.x;
    if (idx >= NN*32) return;
    int n = idx >> 5, j = (idx & 31) << 2;
    size_t si = (size_t)n*F + j;
    float4 s4 = *(const float4*)(g_s + si);
    float4 d4 = *(const float4*)(g_ds + si);
    float4 sv = make_float4(s4.x+d4.x, s4.y+d4.y, s4.z+d4.z, s4.w+d4.w);
    *(float4*)(g_s + si) = sv;
    *(float4*)(g_ds + si) = make_float4(0.f, 0.f, 0.f, 0.f);
    float4 u0 = ld_h4(g_UVo + (size_t)(n*3+0)*256 + j);
    float4 u1 = ld_h4(g_UVo + (size_t)(n*3+1)*256 + j);
    float4 u2 = ld_h4(g_UVo + (size_t)(n*3+2)*256 + j);
    float4 w0 = ld_h4(g_UVo + (size_t)(n*3+0)*256 + 128 + j);
    float4 w1 = ld_h4(g_UVo + (size_t)(n*3+1)*256 + 128 + j);
    float4 w2 = ld_h4(g_UVo + (size_t)(n*3+2)*256 + 128 + j);
    *(float4*)(g_dot + si) = make_float4(u0.x*w0.x + u1.x*w1.x + u2.x*w2.x,
                                         u0.y*w0.y + u1.y*w1.y + u2.y*w2.y,
                                         u0.z*w0.z + u1.z*w1.z + u2.z*w2.z,
                                         u0.w*w0.w + u1.w*w1.w + u2.w*w2.w);
    store_h4(g_minF + (size_t)n*LDW2 + j, sv);
    float4 vn = make_float4(sqrtf(w0.x*w0.x + w1.x*w1.x + w2.x*w2.x),
                            sqrtf(w0.y*w0.y + w1.y*w1.y + w2.y*w2.y),
                            sqrtf(w0.z*w0.z + w1.z*w1.z + w2.z*w2.z),
                            sqrtf(w0.w*w0.w + w1.w*w1.w + w2.w*w2.w));
    store_h4(g_minF + (size_t)n*LDW2 + 128 + j, vn);
}

// s += a_ss + a_sv*dot (also fp16); v = v + dv + a_vv*Uv ; dv=0 ; output
__global__ void final_k(float* __restrict__ out, int l) {
    int idx = blockIdx.x * blockDim.x + threadIdx.x;
    if (idx >= NN*32) return;
    int n = idx >> 5, j = (idx & 31) << 2;
    size_t si = (size_t)n*F + j;
    float4 ass = ld_h4(g_mF + (size_t)n*384 + j);
    float4 asv = ld_h4(g_mF + (size_t)n*384 + 128 + j);
    float4 avv = ld_h4(g_mF + (size_t)n*384 + 256 + j);
    float4 dt  = *(const float4*)(g_dot + si);
    float4 s4  = *(const float4*)(g_s + si);
    float4 sv = make_float4(s4.x + ass.x + asv.x*dt.x,
                            s4.y + ass.y + asv.y*dt.y,
                            s4.z + ass.z + asv.z*dt.z,
                            s4.w + ass.w + asv.w*dt.w);
    *(float4*)(g_s + si) = sv;
    store_h4(g_sF + (size_t)n*LDW1 + j, sv);
    size_t ob = ((size_t)(l*NN + n) * 4) * F + j;
    *(float4*)(out + ob) = sv;
    float4 z = make_float4(0.f, 0.f, 0.f, 0.f);
#pragma unroll
    for (int d = 0; d < 3; d++) {
        size_t vi = (size_t)(n*3 + d)*F + j;
        float4 uv = ld_h4(g_UVo + (size_t)(n*3 + d)*256 + j);
        float4 v4 = *(const float4*)(g_v + vi);
        float4 dv = *(const float4*)(g_dv + vi);
        float4 vv = make_float4(v4.x + dv.x + avv.x*uv.x,
                                v4.y + dv.y + avv.y*uv.y,
                                v4.z + dv.z + avv.z*uv.z,
                                v4.w + dv.w + avv.w*uv.w);
        *(float4*)(g_v + vi) = vv;
        *(float4*)(g_dv + vi) = z;
        *(float4*)(out + ob + (size_t)(d+1)*F) = vv;
    }
}

// ---------------- host launcher ---------------------------------------------
static float* sym(const void* s) { void* p = nullptr; cudaGetSymbolAddress(&p, s); return (float*)p; }

extern "C" void kernel_launch(void* const* d_in, const int* in_sizes, int n_in,
                              void* d_out, int out_size) {
    (void)in_sizes; (void)n_in; (void)out_size;
    const float* atom_xyz = (const float*)d_in[0];
    const float* cell     = (const float*)d_in[1];
    const int*   nodes    = (const int*)  d_in[2];
    const int*   aedges   = (const int*)  d_in[3];
    const float* edisp    = (const float*)d_in[4];
    const float* Vflat    = (const float*)d_in[5];
    const float* Eflat    = (const float*)d_in[6];
    const float* emb      = (const float*)d_in[7];
    const float* potW     = (const float*)d_in[8];
    const float* potb     = (const float*)d_in[9];
    const float* iW1      = (const float*)d_in[10];
    const float* ib1      = (const float*)d_in[11];
    const float* iW2      = (const float*)d_in[12];
    const float* ib2      = (const float*)d_in[13];
    const float* vecw     = (const float*)d_in[14];
    const float* filtW    = (const float*)d_in[15];
    const float* filtb    = (const float*)d_in[16];
    const float* mW1      = (const float*)d_in[17];
    const float* mb1      = (const float*)d_in[18];
    const float* mW2      = (const float*)d_in[19];
    const float* mb2      = (const float*)d_in[20];
    const float* UW       = (const float*)d_in[21];
    const float* VW       = (const float*)d_in[22];
    const float* uW1      = (const float*)d_in[23];
    const float* ub1      = (const float*)d_in[24];
    const float* uW2      = (const float*)d_in[25];
    const float* ub2      = (const float*)d_in[26];
    float* out = (float*)d_out;

    float* ps   = sym(g_s);
    __half* psoF = (__half*)sym(g_soF);
    __half* pmF  = (__half*)sym(g_mF);
    __half* pWSF  = (__half*)sym(g_WSF);
    __half* pminF = (__half*)sym(g_minF);
    __half* phidF = (__half*)sym(g_hidF);
    __half* psF   = (__half*)sym(g_sF);

    cudaFuncSetAttribute((const void*)gemm_hp<1,0,1>,
                         cudaFuncAttributeMaxDynamicSharedMemorySize, GSMEM);
    cudaFuncSetAttribute((const void*)gemm_hp<0,1,1>,
                         cudaFuncAttributeMaxDynamicSharedMemorySize, GSMEM);
    cudaFuncSetAttribute((const void*)gemm_hp<0,0,1>,
                         cudaFuncAttributeMaxDynamicSharedMemorySize, GSMEM);
    cudaFuncSetAttribute((const void*)uv_k,
                         cudaFuncAttributeMaxDynamicSharedMemorySize, GSMEM);

    const int T = 256;
    const int GEO_B  = (ETOT + T - 1) / T;
    const int NF4_B  = (NN*32 + T - 1) / T;
    const int N3F4_B = (NN*3*32 + T - 1) / T;
    const int MB  = NN / 64;       // 256 m-tiles
    const int MB3 = 3*NN / 64;     // 768 m-tiles

    // 1: pack (includes nact reset)  2: geom  3: init_h  4: gemm (profiled)
    pack_all<<<dim3(576, 8), T>>>(iW1, iW2, mW1, mW2, uW1, uW2, UW, VW);
    geom_k<<<GEO_B, T>>>(atom_xyz, cell, aedges, edisp);
    init_h_k<<<NF4_B, T>>>(nodes, Vflat, emb, potW, potb);
    // init1: hid = silu(min @ iW1^T + ib1)
    gemm_hp<1,0,1><<<dim3(1, MB), T, GSMEM>>>(pminF, LDW2,
        pWSF + OFF_IW1, LDW2, ib1, nullptr, phidF, LDW1, F, 2*F);
    // init2: s = hid @ iW2^T + ib2   (f32 + fp16 out)
    gemm_hp<0,1,1><<<dim3(1, MB), T, GSMEM>>>(phidF, LDW1,
        pWSF + OFF_IW2, LDW1, ib2, ps, psF, LDW1, F, F);
    init_v_k<<<N3F4_B, T>>>(Eflat, vecw);

    for (int l = 0; l < NL; l++) {
        size_t lb = OFF_LBASE + (size_t)l*LSTRIDE;
        // msg1: hid = silu(s @ mW1^T + mb1)
        gemm_hp<1,0,1><<<dim3(1, MB), T, GSMEM>>>(psF, LDW1,
            pWSF + lb + LOFF_MW1, LDW1, mb1 + l*F, nullptr, phidF, LDW1, F, F);
        // msg2: so = hid @ mW2^T + mb2   (fp16 out)
        gemm_hp<0,0,1><<<dim3(3, MB), T, GSMEM>>>(phidF, LDW1,
            pWSF + lb + LOFF_MW2, LDW1, mb2 + l*3*F, nullptr, psoF, 384, 3*F, F);
        edge_k<<<EGRID, 128>>>(filtW + (size_t)l*3*F*KF, filtb + (size_t)l*3*F);
        uv_k<<<dim3(2, MB3), T, GSMEM>>>(pWSF + lb + LOFF_UVW);
        prep_k<<<NF4_B, T>>>();
        // upd1: hid = silu(min @ uW1^T + ub1)
        gemm_hp<1,0,1><<<dim3(1, MB), T, GSMEM>>>(pminF, LDW2,
            pWSF + lb + LOFF_UW1, LDW2, ub1 + l*F, nullptr, phidF, LDW1, F, 2*F);
        // upd2: m = hid @ uW2^T + ub2   (fp16 out)
        gemm_hp<0,0,1><<<dim3(3, MB), T, GSMEM>>>(phidF, LDW1,
            pWSF + lb + LOFF_UW2, LDW1, ub2 + l*3*F, nullptr, pmF, 384, 3*F, F);
        final_k<<<NF4_B, T>>>(out, l);
    }
}

// round 17
// speedup vs baseline: 1.4830x; 1.3470x over previous
#include <cuda_runtime.h>
#include <cuda_fp16.h>
#include <math.h>
#include <stdint.h>

#define NB 4
#define NPER 4096
#define EPER 49152
#define NN (NB*NPER)        // 16384 nodes
#define ETOT (NB*EPER)      // 196608 edges
#define F 128
#define KF 20
#define NL 3
#define CUTF 5.0f
#define PIF 3.14159265358979323846f

#define LDW1 136            // row stride (elems) for K=128 planes
#define LDW2 264            // row stride for K=256 planes

// ------------- fp16 weight arena (packed once per launch) -------------------
#define OFF_IW1 0
#define SZ_IW1 (128*LDW2)
#define OFF_IW2 (OFF_IW1 + SZ_IW1)
#define SZ_IW2 (128*LDW1)
#define OFF_LBASE (OFF_IW2 + SZ_IW2)
#define LOFF_MW1 0
#define LOFF_MW2 (128*LDW1)
#define LOFF_UW1 (LOFF_MW2 + 384*LDW1)
#define LOFF_UW2 (LOFF_UW1 + 128*LDW2)
#define LOFF_UVW (LOFF_UW2 + 384*LDW1)
#define LSTRIDE  (LOFF_UVW + 256*LDW1)
#define WARENA   (OFF_LBASE + NL*LSTRIDE)

__device__ __align__(16) __half g_WSF[WARENA];

// ---------------- scratch -----------------------------------------------------
__device__ __align__(16) float g_s  [NN*F];
__device__ __align__(16) float g_v  [NN*3*F];
__device__ __align__(16) float g_ds [NN*F];
__device__ __align__(16) float g_dv [NN*3*F];
__device__ __align__(16) __half g_soF[NN*3*F];     // fp16 message-MLP output
__device__ __align__(16) __half g_mF [NN*3*F];     // fp16 update-MLP output
__device__ __align__(16) __half g_UVo[NN*3*256];   // fp16 Uv|Vv
__device__ __align__(16) float g_dot[NN*F];
__device__ __align__(16) float g_es [ETOT*KF];
__device__ float g_cut[ETOT];
__device__ float g_dir[ETOT*3];
__device__ int   g_send[ETOT];
__device__ int   g_recv[ETOT];
__device__ int   g_nact;
// fp16 activation planes
__device__ __align__(16) __half g_minF[NN*LDW2];   // init MLP input only
__device__ __align__(16) __half g_hidF[NN*LDW1];
__device__ __align__(16) __half g_sF  [NN*LDW1];

// =================== helpers ==================================================
__device__ __forceinline__ uint32_t smem_u32(const void* p) {
    uint32_t a;
    asm("{ .reg .u64 t; cvta.to.shared.u64 t, %1; cvt.u32.u64 %0, t; }"
        : "=r"(a) : "l"(p));
    return a;
}

__device__ __forceinline__ void ldsm4(uint32_t* r, uint32_t addr) {
    asm volatile("ldmatrix.sync.aligned.m8n8.x4.shared.b16 {%0,%1,%2,%3}, [%4];"
        : "=r"(r[0]), "=r"(r[1]), "=r"(r[2]), "=r"(r[3]) : "r"(addr));
}

__device__ __forceinline__ void mma_fp16(float* c, const uint32_t* a, const uint32_t* b) {
    asm volatile("mma.sync.aligned.m16n8k16.row.col.f32.f16.f16.f32 "
        "{%0,%1,%2,%3}, {%4,%5,%6,%7}, {%8,%9}, {%0,%1,%2,%3};"
        : "+f"(c[0]), "+f"(c[1]), "+f"(c[2]), "+f"(c[3])
        : "r"(a[0]), "r"(a[1]), "r"(a[2]), "r"(a[3]), "r"(b[0]), "r"(b[1]));
}

__device__ __forceinline__ void cpa16(uint32_t s, const void* g) {
    asm volatile("cp.async.cg.shared.global [%0], [%1], 16;" :: "r"(s), "l"(g));
}
#define CP_COMMIT asm volatile("cp.async.commit_group;" ::: "memory")
#define CP_WAIT0  asm volatile("cp.async.wait_group 0;"  ::: "memory")
#define CP_WAIT1  asm volatile("cp.async.wait_group 1;"  ::: "memory")

__device__ __forceinline__ uint32_t pack_half2(float x, float y) {
    __half2 h = __floats2half2_rn(x, y);
    return *(uint32_t*)&h;
}

__device__ __forceinline__ void store_h4(__half* p, float4 v) {
    uint2 u;
    u.x = pack_half2(v.x, v.y);
    u.y = pack_half2(v.z, v.w);
    *(uint2*)p = u;
}

__device__ __forceinline__ float4 ld_h4(const __half* p) {
    uint2 u = *(const uint2*)p;
    float2 f0 = __half22float2(*(__half2*)&u.x);
    float2 f1 = __half22float2(*(__half2*)&u.y);
    return make_float4(f0.x, f0.y, f1.x, f1.y);
}

__device__ __forceinline__ float silu(float x) {
    return x / (1.0f + __expf(-x));
}

#define LDA 136
#define ASM_ROWS 64
#define BSM_ROWS 128
#define TSZ_A (ASM_ROWS*LDA)
#define TSZ_B (BSM_ROWS*LDA)
#define GSMEM ((TSZ_A + TSZ_B)*2)            // 52224 B -> 3 CTAs/SM
#define USMEM ((64*LDW2 + TSZ_B)*2)          // 68608 B -> 3 CTAs/SM

// load one half-tile plane (global -> smem, cp.async)
__device__ __forceinline__ void ld_A64(uint32_t aA, const __half* g, int ld,
                                       int buf, int koff, int tid) {
#pragma unroll
    for (int it = 0; it < 2; it++) {
        int gg = tid + it*256;
        int r = gg >> 3, cc = (gg & 7) << 3;
        cpa16(aA + (uint32_t)(r*LDA + buf*64 + cc)*2, g + (size_t)r*ld + koff + cc);
    }
}
__device__ __forceinline__ void ld_B128(uint32_t aB, const __half* g, int ld,
                                        int buf, int koff, int tid) {
#pragma unroll
    for (int it = 0; it < 4; it++) {
        int gg = tid + it*256;
        int r = gg >> 3, cc = (gg & 7) << 3;
        cpa16(aB + (uint32_t)(r*LDA + buf*64 + cc)*2, g + (size_t)r*ld + koff + cc);
    }
}

// 64x128x64 fp16 MMA on one half-buffer; 8 warps (2x4), warp tile 32x32
__device__ __forceinline__ void mma_half16(uint32_t aA, uint32_t aB,
                                           int buf, int wr, int wc, int lane,
                                           float acc[2][4][4]) {
    int arow = lane & 15, acol = (lane >> 4) * 8;
    int bmat = lane >> 3;
    int brow = (bmat >> 1) * 8 + (lane & 7);
    int bcol = (bmat & 1) * 8;
    int cb = buf * 64;
#pragma unroll
    for (int ks = 0; ks < 4; ks++) {
        int k0 = cb + ks * 16;
        uint32_t a0[4], a1[4], b0[4], b1[4];
        ldsm4(a0, aA + (uint32_t)((wr*32 +      arow) * LDA + k0 + acol) * 2);
        ldsm4(a1, aA + (uint32_t)((wr*32 + 16 + arow) * LDA + k0 + acol) * 2);
        ldsm4(b0, aB + (uint32_t)((wc*32 +      brow) * LDA + k0 + bcol) * 2);
        ldsm4(b1, aB + (uint32_t)((wc*32 + 16 + brow) * LDA + k0 + bcol) * 2);
        mma_fp16(acc[0][0], a0, b0); mma_fp16(acc[0][1], a0, b0 + 2);
        mma_fp16(acc[0][2], a0, b1); mma_fp16(acc[0][3], a0, b1 + 2);
        mma_fp16(acc[1][0], a1, b0); mma_fp16(acc[1][1], a1, b0 + 2);
        mma_fp16(acc[1][2], a1, b1); mma_fp16(acc[1][3], a1, b1 + 2);
    }
}

// variant: A stride 264 (full K=256 resident), B standard half-buffer
__device__ __forceinline__ void mma_upd(uint32_t aA, uint32_t aB,
                                        int akoff, int bbuf,
                                        int wr, int wc, int lane,
                                        float acc[2][4][4]) {
    int arow = lane & 15, acol = (lane >> 4) * 8;
    int bmat = lane >> 3;
    int brow = (bmat >> 1) * 8 + (lane & 7);
    int bcol = (bmat & 1) * 8;
    int cbB = bbuf * 64;
#pragma unroll
    for (int ks = 0; ks < 4; ks++) {
        int kA = akoff + ks * 16, kB = cbB + ks * 16;
        uint32_t a0[4], a1[4], b0[4], b1[4];
        ldsm4(a0, aA + (uint32_t)((wr*32 +      arow) * LDW2 + kA + acol) * 2);
        ldsm4(a1, aA + (uint32_t)((wr*32 + 16 + arow) * LDW2 + kA + acol) * 2);
        ldsm4(b0, aB + (uint32_t)((wc*32 +      brow) * LDA + kB + bcol) * 2);
        ldsm4(b1, aB + (uint32_t)((wc*32 + 16 + brow) * LDA + kB + bcol) * 2);
        mma_fp16(acc[0][0], a0, b0); mma_fp16(acc[0][1], a0, b0 + 2);
        mma_fp16(acc[0][2], a0, b1); mma_fp16(acc[0][3], a0, b1 + 2);
        mma_fp16(acc[1][0], a1, b0); mma_fp16(acc[1][1], a1, b0 + 2);
        mma_fp16(acc[1][2], a1, b1); mma_fp16(acc[1][3], a1, b1 + 2);
    }
}

// ====== fp16 GEMM: C = act(A @ W^T + b); CTA tile 64x128, K pipelined =======
template<int ACT, int WF32, int WSPLIT>
__global__ __launch_bounds__(256, 3)
void gemm_hp(const __half* __restrict__ A, int lda,
             const __half* __restrict__ W, int ldw,
             const float* __restrict__ bias, float* __restrict__ C,
             __half* __restrict__ CF, int ldc,
             int Nout, int Kin) {
    extern __shared__ __half sm[];
    __half* Asm = sm;
    __half* Bsm = sm + TSZ_A;
    int tid = threadIdx.x, lane = tid & 31, w = tid >> 5;
    int wr = w >> 2, wc = w & 3;
    int m0 = blockIdx.y * 64, n0 = blockIdx.x * 128;
    uint32_t aA = smem_u32(Asm), aB = smem_u32(Bsm);

    const __half* A0 = A + (size_t)m0 * lda;
    const __half* B0 = W + (size_t)n0 * ldw;

#define LOADH(buf, kh) do { int _ko = (kh)*64;        \
        ld_A64(aA, A0, lda, (buf), _ko, tid);         \
        ld_B128(aB, B0, ldw, (buf), _ko, tid);        \
        CP_COMMIT; } while (0)

    int NH = Kin >> 6;
    float acc[2][4][4] = {};
    LOADH(0, 0);
    if (NH > 1) LOADH(1, 1);
    for (int kh = 0; kh < NH; kh++) {
        if (kh + 1 < NH) { CP_WAIT1; } else { CP_WAIT0; }
        __syncthreads();
        mma_half16(aA, aB, kh & 1, wr, wc, lane, acc);
        if (kh + 2 < NH) {
            __syncthreads();
            LOADH(kh & 1, kh + 2);
        }
    }
#undef LOADH

#pragma unroll
    for (int ni = 0; ni < 4; ni++) {
        int c = wc*32 + ni*8 + (lane & 3) * 2;
        float b0 = bias[n0 + c], b1 = bias[n0 + c + 1];
#pragma unroll
        for (int mi = 0; mi < 2; mi++) {
            int r0 = m0 + wr*32 + mi*16 + (lane >> 2);
            float o0 = acc[mi][ni][0] + b0;
            float o1 = acc[mi][ni][1] + b1;
            float o2 = acc[mi][ni][2] + b0;
            float o3 = acc[mi][ni][3] + b1;
            if (ACT) {
                o0 = silu(o0); o1 = silu(o1);
                o2 = silu(o2); o3 = silu(o3);
            }
            if (WF32) {
                *(float2*)(C + (size_t)r0 * Nout + n0 + c)       = make_float2(o0, o1);
                *(float2*)(C + (size_t)(r0 + 8) * Nout + n0 + c) = make_float2(o2, o3);
            }
            if (WSPLIT) {
                *(uint32_t*)&CF[(size_t)r0*ldc + n0 + c]     = pack_half2(o0, o1);
                *(uint32_t*)&CF[(size_t)(r0+8)*ldc + n0 + c] = pack_half2(o2, o3);
            }
        }
    }
}

// === fused prep + upd1: hid = silu([s+ds, Vn] @ uW1^T + b); also s,dot,ds ===
__global__ __launch_bounds__(256, 3)
void upd1_k(const __half* __restrict__ W,   // 128 x LDW2 fp16
            const float* __restrict__ bias,
            __half* __restrict__ CF) {      // hidF
    extern __shared__ __half sm[];
    __half* Asm = sm;                 // 64 x LDW2
    __half* Bsm = sm + 64*LDW2;       // 128 x LDA (two 64-col halves)
    int tid = threadIdx.x, lane = tid & 31, w = tid >> 5;
    int wr = w >> 2, wc = w & 3;
    int m0 = blockIdx.x * 64;
    uint32_t aA = smem_u32(Asm), aB = smem_u32(Bsm);

    // B halves 0,1 in flight while computing A
    ld_B128(aB, W, LDW2, 0, 0, tid);  CP_COMMIT;
    ld_B128(aB, W, LDW2, 1, 64, tid); CP_COMMIT;

    // A = [s+ds | Vn], computed in-loader; persist s, dot; zero ds
    for (int g = tid; g < 4096; g += 256) {
        int row = g >> 6, grp = g & 63;
        int n = m0 + row;
        if (grp < 32) {
            int j = grp << 2;
            size_t si = (size_t)n*F + j;
            float4 s4 = *(const float4*)(g_s + si);
            float4 d4 = *(const float4*)(g_ds + si);
            float4 sv = make_float4(s4.x+d4.x, s4.y+d4.y, s4.z+d4.z, s4.w+d4.w);
            *(float4*)(g_s + si) = sv;
            *(float4*)(g_ds + si) = make_float4(0.f, 0.f, 0.f, 0.f);
            store_h4(Asm + (size_t)row*LDW2 + j, sv);
        } else {
            int j = (grp - 32) << 2;
            float4 u0 = ld_h4(g_UVo + (size_t)(n*3+0)*256 + j);
            float4 u1 = ld_h4(g_UVo + (size_t)(n*3+1)*256 + j);
            float4 u2 = ld_h4(g_UVo + (size_t)(n*3+2)*256 + j);
            float4 w0 = ld_h4(g_UVo + (size_t)(n*3+0)*256 + 128 + j);
            float4 w1 = ld_h4(g_UVo + (size_t)(n*3+1)*256 + 128 + j);
            float4 w2 = ld_h4(g_UVo + (size_t)(n*3+2)*256 + 128 + j);
            *(float4*)(g_dot + (size_t)n*F + j)
                = make_float4(u0.x*w0.x + u1.x*w1.x + u2.x*w2.x,
                              u0.y*w0.y + u1.y*w1.y + u2.y*w2.y,
                              u0.z*w0.z + u1.z*w1.z + u2.z*w2.z,
                              u0.w*w0.w + u1.w*w1.w + u2.w*w2.w);
            float4 vn = make_float4(sqrtf(w0.x*w0.x + w1.x*w1.x + w2.x*w2.x),
                                    sqrtf(w0.y*w0.y + w1.y*w1.y + w2.y*w2.y),
                                    sqrtf(w0.z*w0.z + w1.z*w1.z + w2.z*w2.z),
                                    sqrtf(w0.w*w0.w + w1.w*w1.w + w2.w*w2.w));
            store_h4(Asm + (size_t)row*LDW2 + 128 + j, vn);
        }
    }

    float acc[2][4][4] = {};
    for (int kh = 0; kh < 4; kh++) {
        if (kh + 1 < 4) { CP_WAIT1; } else { CP_WAIT0; }
        __syncthreads();
        mma_upd(aA, aB, kh*64, kh & 1, wr, wc, lane, acc);
        if (kh + 2 < 4) {
            __syncthreads();
            ld_B128(aB, W, LDW2, kh & 1, (kh + 2)*64, tid);
            CP_COMMIT;
        }
    }

#pragma unroll
    for (int ni = 0; ni < 4; ni++) {
        int c = wc*32 + ni*8 + (lane & 3) * 2;
        float b0 = bias[c], b1 = bias[c + 1];
#pragma unroll
        for (int mi = 0; mi < 2; mi++) {
            int r0 = m0 + wr*32 + mi*16 + (lane >> 2);
            float o0 = silu(acc[mi][ni][0] + b0);
            float o1 = silu(acc[mi][ni][1] + b1);
            float o2 = silu(acc[mi][ni][2] + b0);
            float o3 = silu(acc[mi][ni][3] + b1);
            *(uint32_t*)&CF[(size_t)r0*LDW1 + c]     = pack_half2(o0, o1);
            *(uint32_t*)&CF[(size_t)(r0+8)*LDW1 + c] = pack_half2(o2, o3);
        }
    }
}

// ======= UV GEMM: [Uv|Vv] = (v+dv) @ [UW|VW]^T ; tile 64x128, fp16 out =====
__global__ __launch_bounds__(256, 3)
void uv_k(const __half* __restrict__ W) {
    extern __shared__ __half sm[];
    __half* Asm = sm;
    __half* Bsm = sm + TSZ_A;
    int tid = threadIdx.x, lane = tid & 31, w = tid >> 5;
    int wr = w >> 2, wc = w & 3;
    int m0 = blockIdx.y * 64, n0 = blockIdx.x * 128;
    uint32_t aA = smem_u32(Asm), aB = smem_u32(Bsm);

#pragma unroll
    for (int it = 0; it < 8; it++) {
        int gg = tid + it*256;
        int r = gg >> 4, cc = (gg & 15) << 3;
        cpa16(aB + (uint32_t)(r*LDA + cc)*2, W + (size_t)(n0 + r) * LDW1 + cc);
    }
    CP_COMMIT;
#pragma unroll
    for (int g = tid; g < 2048; g += 256) {
        int row = g >> 5, col = (g & 31) << 2;
        size_t ai = (size_t)(m0 + row) * 128 + col;
        float4 a1 = *(const float4*)(g_v + ai);
        float4 a2 = *(const float4*)(g_dv + ai);
        store_h4(Asm + row*LDA + col,
                 make_float4(a1.x+a2.x, a1.y+a2.y, a1.z+a2.z, a1.w+a2.w));
    }
    CP_WAIT0;
    __syncthreads();
    float acc[2][4][4] = {};
    mma_half16(aA, aB, 0, wr, wc, lane, acc);
    mma_half16(aA, aB, 1, wr, wc, lane, acc);

#pragma unroll
    for (int ni = 0; ni < 4; ni++) {
        int c = n0 + wc*32 + ni*8 + (lane & 3) * 2;
#pragma unroll
        for (int mi = 0; mi < 2; mi++) {
            int r0 = m0 + wr*32 + mi*16 + (lane >> 2);
            *(uint32_t*)&g_UVo[(size_t)r0 * 256 + c]
                = pack_half2(acc[mi][ni][0], acc[mi][ni][1]);
            *(uint32_t*)&g_UVo[(size_t)(r0 + 8) * 256 + c]
                = pack_half2(acc[mi][ni][2], acc[mi][ni][3]);
        }
    }
}

// ---------------- pack all weights into fp16 arena (+ reset) ----------------
__global__ void pack_all(const float* __restrict__ iW1, const float* __restrict__ iW2,
                         const float* __restrict__ mW1, const float* __restrict__ mW2,
                         const float* __restrict__ uW1, const float* __restrict__ uW2,
                         const float* __restrict__ UW,  const float* __restrict__ VW) {
    int idx = blockIdx.x * blockDim.x + threadIdx.x;
    int region = blockIdx.y;
    if (region == 0 && idx == 0) g_nact = 0;
    switch (region) {
    case 0: if (idx < 128*256) {
        int n = idx >> 8, k = idx & 255;
        g_WSF[OFF_IW1 + (size_t)n*LDW2 + k] = __float2half_rn(iW1[idx]);
    } break;
    case 1: if (idx < 128*128) {
        int n = idx >> 7, k = idx & 127;
        g_WSF[OFF_IW2 + (size_t)n*LDW1 + k] = __float2half_rn(iW2[idx]);
    } break;
    case 2: if (idx < NL*128*128) {
        int l = idx / 16384, r = idx % 16384, n = r >> 7, k = r & 127;
        g_WSF[OFF_LBASE + (size_t)l*LSTRIDE + LOFF_MW1 + (size_t)n*LDW1 + k] = __float2half_rn(mW1[idx]);
    } break;
    case 3: if (idx < NL*384*128) {
        int l = idx / 49152, r = idx % 49152, n = r >> 7, k = r & 127;
        g_WSF[OFF_LBASE + (size_t)l*LSTRIDE + LOFF_MW2 + (size_t)n*LDW1 + k] = __float2half_rn(mW2[idx]);
    } break;
    case 4: if (idx < NL*128*256) {
        int l = idx / 32768, r = idx % 32768, n = r >> 8, k = r & 255;
        g_WSF[OFF_LBASE + (size_t)l*LSTRIDE + LOFF_UW1 + (size_t)n*LDW2 + k] = __float2half_rn(uW1[idx]);
    } break;
    case 5: if (idx < NL*384*128) {
        int l = idx / 49152, r = idx % 49152, n = r >> 7, k = r & 127;
        g_WSF[OFF_LBASE + (size_t)l*LSTRIDE + LOFF_UW2 + (size_t)n*LDW1 + k] = __float2half_rn(uW2[idx]);
    } break;
    case 6: if (idx < NL*128*128) {
        int l = idx / 16384, r = idx % 16384, n = r >> 7, k = r & 127;
        g_WSF[OFF_LBASE + (size_t)l*LSTRIDE + LOFF_UVW + (size_t)n*LDW1 + k] = __float2half_rn(UW[idx]);
    } break;
    case 7: if (idx < NL*128*128) {
        int l = idx / 16384, r = idx % 16384, n = r >> 7, k = r & 127;
        g_WSF[OFF_LBASE + (size_t)l*LSTRIDE + LOFF_UVW + (size_t)(128+n)*LDW1 + k] = __float2half_rn(VW[idx]);
    } break;
    }
}

// ---------------- misc kernels ------------------------------------------------
__global__ void geom_k(const float* __restrict__ xyz, const float* __restrict__ cell,
                       const int* __restrict__ aedges, const float* __restrict__ edisp) {
    int e = blockIdx.x * blockDim.x + threadIdx.x;
    if (e >= ETOT) return;
    int b = e / EPER;
    int snd = aedges[2*e]   + b * NPER;
    int rcv = aedges[2*e+1] + b * NPER;
    const float* cb = cell + b * 9;
    float c0 = edisp[3*e], c1 = edisp[3*e+1], c2 = edisp[3*e+2];
    float dx[3];
#pragma unroll
    for (int d = 0; d < 3; d++) {
        float disp = c0 * cb[d] + c1 * cb[3+d] + c2 * cb[6+d];
        dx[d] = xyz[3*rcv+d] - (xyz[3*snd+d] + disp);
    }
    float dist = sqrtf(dx[0]*dx[0] + dx[1]*dx[1] + dx[2]*dx[2]);
    if (dist < CUTF) {
        int p = atomicAdd(&g_nact, 1);
        g_send[p] = snd; g_recv[p] = rcv;
        float inv  = 1.0f / dist;
        float invm = 1.0f / fmaxf(dist, 1e-12f);
#pragma unroll
        for (int k = 0; k < KF; k++)
            g_es[p*KF+k] = sinf(dist * (float)(k+1) * (PIF/CUTF)) * inv;
        g_cut[p] = 0.5f * (cosf(PIF * dist / CUTF) + 1.0f);
        g_dir[3*p]   = dx[0]*invm;
        g_dir[3*p+1] = dx[1]*invm;
        g_dir[3*p+2] = dx[2]*invm;
    }
}

// h = [atom_emb[node], V*potW + potb] -> fp16 g_min
__global__ void init_h_k(const int* __restrict__ nodes, const float* __restrict__ Vflat,
                         const float* __restrict__ emb, const float* __restrict__ potW,
                         const float* __restrict__ potb) {
    int idx = blockIdx.x * blockDim.x + threadIdx.x;
    if (idx >= NN*32) return;
    int n = idx >> 5, j = (idx & 31) << 2;
    float4 ev = *(const float4*)(emb + (size_t)nodes[n]*F + j);
    store_h4(g_minF + (size_t)n*LDW2 + j, ev);
    float vf = Vflat[n];
    float4 pw = *(const float4*)(potW + j);
    float4 pb = *(const float4*)(potb + j);
    float4 pv = make_float4(vf*pw.x+pb.x, vf*pw.y+pb.y, vf*pw.z+pb.z, vf*pw.w+pb.w);
    store_h4(g_minF + (size_t)n*LDW2 + 128 + j, pv);
}

__global__ void init_v_k(const float* __restrict__ Eflat, const float* __restrict__ vecw) {
    int idx = blockIdx.x * blockDim.x + threadIdx.x;
    if (idx >= NN*3*32) return;
    int r = idx >> 5, j = (idx & 31) << 2;
    float e = Eflat[r];
    float4 w = *(const float4*)(vecw + j);
    *(float4*)(g_v + (size_t)r*F + j) = make_float4(e*w.x, e*w.y, e*w.z, e*w.w);
}

// one edge per block-iteration; per-thread filter rows held in registers.
#define EGRID 4096
__global__ __launch_bounds__(128)
void edge_k(const float* __restrict__ fW, const float* __restrict__ fb) {
    int nact = g_nact;
    if (blockIdx.x >= nact) return;
    int j = threadIdx.x;
    float fb0 = fb[j], fb1 = fb[j+128], fb2 = fb[j+256];
    float w0[KF], w1[KF], w2[KF];
    const float* w0p = fW + (size_t)j*KF;
    const float* w1p = fW + (size_t)(j+128)*KF;
    const float* w2p = fW + (size_t)(j+256)*KF;
#pragma unroll
    for (int k = 0; k < KF; k++) { w0[k] = w0p[k]; w1[k] = w1p[k]; w2[k] = w2p[k]; }

    for (int e = blockIdx.x; e < nact; e += EGRID) {
        int snd = g_send[e], rcv = g_recv[e];
        float cutv = g_cut[e];
        float esr[KF];
#pragma unroll
        for (int k = 0; k < KF; k++) esr[k] = g_es[e*KF+k];
        float fw0 = fb0, fw1 = fb1, fw2 = fb2;
#pragma unroll
        for (int k = 0; k < KF; k++) {
            fw0 += w0[k] * esr[k];
            fw1 += w1[k] * esr[k];
            fw2 += w2[k] * esr[k];
        }
        const __half* sop = g_soF + (size_t)snd * 384;
        float gsv = fw0 * cutv * __half2float(sop[j]);
        float gev = fw1 * cutv * __half2float(sop[j+128]);
        float gns = fw2 * cutv * __half2float(sop[j+256]);
        atomicAdd(&g_ds[rcv*F + j], g_s[snd*F + j] * gns);
        float d0 = g_dir[3*e], d1 = g_dir[3*e+1], d2 = g_dir[3*e+2];
        atomicAdd(&g_dv[(rcv*3+0)*F + j], g_v[(snd*3+0)*F + j]*gsv + gev*d0);
        atomicAdd(&g_dv[(rcv*3+1)*F + j], g_v[(snd*3+1)*F + j]*gsv + gev*d1);
        atomicAdd(&g_dv[(rcv*3+2)*F + j], g_v[(snd*3+2)*F + j]*gsv + gev*d2);
    }
}

// s += a_ss + a_sv*dot (also fp16); v = v + dv + a_vv*Uv ; dv=0 ; output
__global__ void final_k(float* __restrict__ out, int l) {
    int idx = blockIdx.x * blockDim.x + threadIdx.x;
    if (idx >= NN*32) return;
    int n = idx >> 5, j = (idx & 31) << 2;
    size_t si = (size_t)n*F + j;
    float4 ass = ld_h4(g_mF + (size_t)n*384 + j);
    float4 asv = ld_h4(g_mF + (size_t)n*384 + 128 + j);
    float4 avv = ld_h4(g_mF + (size_t)n*384 + 256 + j);
    float4 dt  = *(const float4*)(g_dot + si);
    float4 s4  = *(const float4*)(g_s + si);
    float4 sv = make_float4(s4.x + ass.x + asv.x*dt.x,
                            s4.y + ass.y + asv.y*dt.y,
                            s4.z + ass.z + asv.z*dt.z,
                            s4.w + ass.w + asv.w*dt.w);
    *(float4*)(g_s + si) = sv;
    store_h4(g_sF + (size_t)n*LDW1 + j, sv);
    size_t ob = ((size_t)(l*NN + n) * 4) * F + j;
    *(float4*)(out + ob) = sv;
    float4 z = make_float4(0.f, 0.f, 0.f, 0.f);
#pragma unroll
    for (int d = 0; d < 3; d++) {
        size_t vi = (size_t)(n*3 + d)*F + j;
        float4 uv = ld_h4(g_UVo + (size_t)(n*3 + d)*256 + j);
        float4 v4 = *(const float4*)(g_v + vi);
        float4 dv = *(const float4*)(g_dv + vi);
        float4 vv = make_float4(v4.x + dv.x + avv.x*uv.x,
                                v4.y + dv.y + avv.y*uv.y,
                                v4.z + dv.z + avv.z*uv.z,
                                v4.w + dv.w + avv.w*uv.w);
        *(float4*)(g_v + vi) = vv;
        *(float4*)(g_dv + vi) = z;
        *(float4*)(out + ob + (size_t)(d+1)*F) = vv;
    }
}

// ---------------- host launcher ---------------------------------------------
static float* sym(const void* s) { void* p = nullptr; cudaGetSymbolAddress(&p, s); return (float*)p; }

extern "C" void kernel_launch(void* const* d_in, const int* in_sizes, int n_in,
                              void* d_out, int out_size) {
    (void)in_sizes; (void)n_in; (void)out_size;
    const float* atom_xyz = (const float*)d_in[0];
    const float* cell     = (const float*)d_in[1];
    const int*   nodes    = (const int*)  d_in[2];
    const int*   aedges   = (const int*)  d_in[3];
    const float* edisp    = (const float*)d_in[4];
    const float* Vflat    = (const float*)d_in[5];
    const float* Eflat    = (const float*)d_in[6];
    const float* emb      = (const float*)d_in[7];
    const float* potW     = (const float*)d_in[8];
    const float* potb     = (const float*)d_in[9];
    const float* iW1      = (const float*)d_in[10];
    const float* ib1      = (const float*)d_in[11];
    const float* iW2      = (const float*)d_in[12];
    const float* ib2      = (const float*)d_in[13];
    const float* vecw     = (const float*)d_in[14];
    const float* filtW    = (const float*)d_in[15];
    const float* filtb    = (const float*)d_in[16];
    const float* mW1      = (const float*)d_in[17];
    const float* mb1      = (const float*)d_in[18];
    const float* mW2      = (const float*)d_in[19];
    const float* mb2      = (const float*)d_in[20];
    const float* UW       = (const float*)d_in[21];
    const float* VW       = (const float*)d_in[22];
    const float* uW1      = (const float*)d_in[23];
    const float* ub1      = (const float*)d_in[24];
    const float* uW2      = (const float*)d_in[25];
    const float* ub2      = (const float*)d_in[26];
    float* out = (float*)d_out;

    float* ps   = sym(g_s);
    __half* psoF = (__half*)sym(g_soF);
    __half* pmF  = (__half*)sym(g_mF);
    __half* pWSF  = (__half*)sym(g_WSF);
    __half* pminF = (__half*)sym(g_minF);
    __half* phidF = (__half*)sym(g_hidF);
    __half* psF   = (__half*)sym(g_sF);

    cudaFuncSetAttribute((const void*)gemm_hp<1,0,1>,
                         cudaFuncAttributeMaxDynamicSharedMemorySize, GSMEM);
    cudaFuncSetAttribute((const void*)gemm_hp<0,1,1>,
                         cudaFuncAttributeMaxDynamicSharedMemorySize, GSMEM);
    cudaFuncSetAttribute((const void*)gemm_hp<0,0,1>,
                         cudaFuncAttributeMaxDynamicSharedMemorySize, GSMEM);
    cudaFuncSetAttribute((const void*)uv_k,
                         cudaFuncAttributeMaxDynamicSharedMemorySize, GSMEM);
    cudaFuncSetAttribute((const void*)upd1_k,
                         cudaFuncAttributeMaxDynamicSharedMemorySize, USMEM);

    const int T = 256;
    const int GEO_B  = (ETOT + T - 1) / T;
    const int NF4_B  = (NN*32 + T - 1) / T;
    const int N3F4_B = (NN*3*32 + T - 1) / T;
    const int MB  = NN / 64;       // 256 m-tiles
    const int MB3 = 3*NN / 64;     // 768 m-tiles

    // 1: pack (includes nact reset)  2: geom  3: init_h  4: gemm (profiled)
    pack_all<<<dim3(576, 8), T>>>(iW1, iW2, mW1, mW2, uW1, uW2, UW, VW);
    geom_k<<<GEO_B, T>>>(atom_xyz, cell, aedges, edisp);
    init_h_k<<<NF4_B, T>>>(nodes, Vflat, emb, potW, potb);
    // init1: hid = silu(min @ iW1^T + ib1)
    gemm_hp<1,0,1><<<dim3(1, MB), T, GSMEM>>>(pminF, LDW2,
        pWSF + OFF_IW1, LDW2, ib1, nullptr, phidF, LDW1, F, 2*F);
    // init2: s = hid @ iW2^T + ib2   (f32 + fp16 out)
    gemm_hp<0,1,1><<<dim3(1, MB), T, GSMEM>>>(phidF, LDW1,
        pWSF + OFF_IW2, LDW1, ib2, ps, psF, LDW1, F, F);
    init_v_k<<<N3F4_B, T>>>(Eflat, vecw);

    for (int l = 0; l < NL; l++) {
        size_t lb = OFF_LBASE + (size_t)l*LSTRIDE;
        // msg1: hid = silu(s @ mW1^T + mb1)
        gemm_hp<1,0,1><<<dim3(1, MB), T, GSMEM>>>(psF, LDW1,
            pWSF + lb + LOFF_MW1, LDW1, mb1 + l*F, nullptr, phidF, LDW1, F, F);
        // msg2: so = hid @ mW2^T + mb2   (fp16 out)
        gemm_hp<0,0,1><<<dim3(3, MB), T, GSMEM>>>(phidF, LDW1,
            pWSF + lb + LOFF_MW2, LDW1, mb2 + l*3*F, nullptr, psoF, 384, 3*F, F);
        edge_k<<<EGRID, 128>>>(filtW + (size_t)l*3*F*KF, filtb + (size_t)l*3*F);
        uv_k<<<dim3(2, MB3), T, GSMEM>>>(pWSF + lb + LOFF_UVW);
        // fused prep + upd1
        upd1_k<<<MB, T, USMEM>>>(pWSF + lb + LOFF_UW1, ub1 + l*F, phidF);
        // upd2: m = hid @ uW2^T + ub2   (fp16 out)
        gemm_hp<0,0,1><<<dim3(3, MB), T, GSMEM>>>(phidF, LDW1,
            pWSF + lb + LOFF_UW2, LDW1, ub2 + l*3*F, nullptr, pmF, 384, 3*F, F);
        final_k<<<NF4_B, T>>>(out, l);
    }
}